// round 10
// baseline (speedup 1.0000x reference)
#include <cuda_runtime.h>
#include <cuda_fp16.h>
#include <cstdint>
#include <math.h>

#define BB 256
#define TT 40
#define DD 100
#define D2 200
#define NNODE 200000
#define NOUT 199999   // N_NODE - 1

// scratch for ma [256][200], 16B-aligned for float4 loads
__device__ __align__(16) float g_ma[BB * D2];

// ---------------------------------------------------------------------------
// helpers
// ---------------------------------------------------------------------------
__device__ __forceinline__ unsigned long long pack2(float lo, float hi) {
    unsigned long long r;
    asm("mov.b64 %0, {%1,%2};" : "=l"(r) : "f"(lo), "f"(hi));
    return r;
}
__device__ __forceinline__ void ffma2(unsigned long long& d,
                                      unsigned long long a, unsigned long long b) {
    asm("fma.rn.f32x2 %0, %1, %2, %0;" : "+l"(d) : "l"(a), "l"(b));
}
__device__ __forceinline__ float2 unpack2(unsigned long long v) {
    float2 f;
    asm("mov.b64 {%0,%1}, %2;" : "=f"(f.x), "=f"(f.y) : "l"(v));
    return f;
}

// fp16 m16n8k16 mma: A 4 regs, B 2 regs, C/D 4 fp32
__device__ __forceinline__ void mma_f16(float d[4],
                                        uint32_t a0, uint32_t a1, uint32_t a2, uint32_t a3,
                                        uint32_t b0, uint32_t b1) {
    asm volatile(
        "mma.sync.aligned.m16n8k16.row.col.f32.f16.f16.f32 "
        "{%0,%1,%2,%3}, {%4,%5,%6,%7}, {%8,%9}, {%0,%1,%2,%3};\n"
        : "+f"(d[0]), "+f"(d[1]), "+f"(d[2]), "+f"(d[3])
        : "r"(a0), "r"(a1), "r"(a2), "r"(a3), "r"(b0), "r"(b1));
}

__device__ __forceinline__ void ldsm_x4(uint32_t& r0, uint32_t& r1,
                                        uint32_t& r2, uint32_t& r3, uint32_t addr) {
    asm volatile("ldmatrix.sync.aligned.m8n8.x4.shared.b16 {%0,%1,%2,%3}, [%4];"
                 : "=r"(r0), "=r"(r1), "=r"(r2), "=r"(r3) : "r"(addr));
}

// 8 fp32 -> 8 halves -> one STS.128
__device__ __forceinline__ void sts_h8(uint32_t addr, float4 a, float4 b) {
    __half2 h0 = __float22half2_rn(make_float2(a.x, a.y));
    __half2 h1 = __float22half2_rn(make_float2(a.z, a.w));
    __half2 h2 = __float22half2_rn(make_float2(b.x, b.y));
    __half2 h3 = __float22half2_rn(make_float2(b.z, b.w));
    uint32_t u0 = *reinterpret_cast<uint32_t*>(&h0);
    uint32_t u1 = *reinterpret_cast<uint32_t*>(&h1);
    uint32_t u2 = *reinterpret_cast<uint32_t*>(&h2);
    uint32_t u3 = *reinterpret_cast<uint32_t*>(&h3);
    asm volatile("st.shared.v4.b32 [%0], {%1,%2,%3,%4};"
                 :: "r"(addr), "r"(u0), "r"(u1), "r"(u2), "r"(u3) : "memory");
}

// ---------------------------------------------------------------------------
// Phase 1: one CTA per batch element (256 CTAs); writes g_ma[b][0..199]
// ---------------------------------------------------------------------------
__global__ __launch_bounds__(256) void phase1_kernel(
    const float* __restrict__ re,     // [B,U,D]
    const float* __restrict__ ret,    // [B,U,D]
    const float* __restrict__ mask,   // [B,T]
    const float* __restrict__ maskt,  // [B,T]
    const int*   __restrict__ alias,  // [B,T]
    const int*   __restrict__ aliast, // [B,T]
    const float* __restrict__ w1,     // [2D,2D]
    const float* __restrict__ w2,     // [2D,2D]
    const float* __restrict__ w3,     // [2D,2D]
    const float* __restrict__ v,      // [2D]
    const float* __restrict__ bias)   // [2D]
{
    extern __shared__ float sm1[];
    float* sh    = sm1;            // [40][200]
    float* cbuf  = sm1 + 8000;     // [40][200]
    float* coefs = sm1 + 16000;    // [40]
    float* svec  = sm1 + 16040;    // [200]
    float* lastv = sm1 + 16240;    // [200]
    __shared__ int sa[TT], sat[TT], slast[2];

    const int b = blockIdx.x;
    const int tid = threadIdx.x;
    const int j = tid;

    if (tid < TT) {
        sa[tid]  = alias[b * TT + tid];
        sat[tid] = aliast[b * TT + tid];
    }
    if (tid == 0) {
        float s = 0.f, st = 0.f;
        for (int t = 0; t < TT; t++) { s += mask[b * TT + t]; st += maskt[b * TT + t]; }
        int rm  = (int)(s  + 0.5f); rm  = rm  < 1 ? 1 : (rm  > TT ? TT : rm);
        int rmt = (int)(st + 0.5f); rmt = rmt < 1 ? 1 : (rmt > TT ? TT : rmt);
        slast[0] = alias[b * TT + rm - 1];
        slast[1] = aliast[b * TT + rmt - 1];
    }
    __syncthreads();

    for (int idx = tid; idx < TT * D2; idx += 256) {
        int t = idx / D2, k = idx - t * D2;
        sh[idx] = (k < DD) ? re[(b * TT + sa[t]) * DD + k]
                           : ret[(b * TT + sat[t]) * DD + (k - DD)];
    }
    if (tid < D2) {
        lastv[tid] = (tid < DD) ? re[(b * TT + slast[0]) * DD + tid]
                                : ret[(b * TT + slast[1]) * DD + (tid - DD)];
    }
    __syncthreads();

    float lpj = 0.f;
    if (j < D2) {
        for (int k = 0; k < D2; k++) lpj += lastv[k] * w1[k * D2 + j];
    }

    if (j < D2) {
        unsigned long long acc2[TT];
        const unsigned long long z = pack2(0.f, 0.f);
#pragma unroll
        for (int t = 0; t < TT; t++) acc2[t] = z;
        for (int k = 0; k < D2; k += 4) {
            unsigned long long w01 = pack2(w2[(k + 0) * D2 + j], w2[(k + 1) * D2 + j]);
            unsigned long long w23 = pack2(w2[(k + 2) * D2 + j], w2[(k + 3) * D2 + j]);
#pragma unroll
            for (int t = 0; t < TT; t++) {
                ulonglong2 s2 = *(const ulonglong2*)&sh[t * D2 + k];
                ffma2(acc2[t], s2.x, w01);
                ffma2(acc2[t], s2.y, w23);
            }
        }
        float vj = v[j], bj = bias[j];
#pragma unroll
        for (int t = 0; t < TT; t++) {
            float2 u = unpack2(acc2[t]);
            float x = lpj + u.x + u.y + bj;
            float e = __expf(-x);
            float mval = __fdividef(1.f, 1.f + e);
            cbuf[t * D2 + j] = mval * vj;
        }
    }
    __syncthreads();

    if (tid < TT) {
        float c = 0.f;
        for (int jj = 0; jj < D2; jj++) c += cbuf[tid * D2 + jj];
        coefs[tid] = c * mask[b * TT + tid];
    }
    __syncthreads();

    if (tid < D2) {
        float s = 0.f;
#pragma unroll
        for (int t = 0; t < TT; t++) s += coefs[t] * sh[t * D2 + tid];
        svec[tid] = s;
    }
    __syncthreads();

    if (j < D2) {
        float m = 0.f;
        for (int k = 0; k < D2; k++) m += svec[k] * w3[k * D2 + j];
        g_ma[b * D2 + j] = m;
    }
}

// ---------------------------------------------------------------------------
// Phase 2: logits[256][199999] = ma @ b_emb^T via fp16 mma.m16n8k16.
// BM=BN=128. K=200 padded to 224 halves, 2 chunks of 112 (7 k16-steps each),
// single-buffered. fp16 tiles, row stride 240 B (conflict-free for ldmatrix).
// Epilogue via smem transpose -> coalesced 128B warp stores.
// ---------------------------------------------------------------------------
#define RSTRB 240                 // row stride bytes (120 halves)
#define TILEB (128 * RSTRB)       // 30720 B per tile
#define SCT_OFF 67584             // after epilogue Cs region (128*132*4)
#define P2_SMEM (SCT_OFF + 512 + 64)
#define CSTR  132                 // epilogue smem stride (floats)

__global__ __launch_bounds__(256, 2) void phase2_kernel(
    const float* __restrict__ emb,    // [N_NODE, 100]
    const float* __restrict__ embt,   // [N_TYPE, 100]
    const int*   __restrict__ csort,  // [N_NODE]
    float* __restrict__ out)          // [256, 199999]
{
    extern __shared__ __align__(16) float sm2[];
    const uint32_t sb = (uint32_t)__cvta_generic_to_shared(sm2);
    int* sct = (int*)((char*)sm2 + SCT_OFF);

    const int tid  = threadIdx.x;
    const int wid  = tid >> 5;
    const int lane = tid & 31;
    const int m0   = blockIdx.x * 128;   // batch tile
    const int n0   = blockIdx.y * 128;   // node tile
    const int wm = wid >> 2;   // 0..1 -> 64 rows (batch)
    const int wn = wid & 3;    // 0..3 -> 32 cols (nodes)

    for (int i = tid; i < 128; i += 256) {
        int n = n0 + i + 1; if (n > NNODE - 1) n = NNODE - 1;
        sct[i] = csort[n];
    }
    __syncthreads();

    const float4* emb4  = (const float4*)emb;
    const float4* embt4 = (const float4*)embt;
    const float4* ma4   = (const float4*)g_ma;
    const float4 f4z = make_float4(0.f, 0.f, 0.f, 0.f);

    // fragment base addresses (A = ma tile at sb, B = node tile at sb+TILEB)
    uint32_t baseA[4], baseB[2];
#pragma unroll
    for (int mt = 0; mt < 4; mt++) {
        int row = wm * 64 + mt * 16 + (lane & 15);
        baseA[mt] = sb + (uint32_t)(row * RSTRB) + (uint32_t)(((lane >> 4) & 1) * 16);
    }
#pragma unroll
    for (int p = 0; p < 2; p++) {
        int row = wn * 32 + p * 16 + ((lane >> 4) & 1) * 8 + (lane & 7);
        baseB[p] = sb + (uint32_t)TILEB + (uint32_t)(row * RSTRB)
                 + (uint32_t)(((lane >> 3) & 1) * 16);
    }

    float acc[4][4][4];
#pragma unroll
    for (int mt = 0; mt < 4; mt++)
#pragma unroll
        for (int nt = 0; nt < 4; nt++)
#pragma unroll
            for (int r = 0; r < 4; r++) acc[mt][nt][r] = 0.f;

    for (int c = 0; c < 2; c++) {
        if (c) __syncthreads();  // all reads of chunk 0 done before overwrite

        // ---- stage A tile: ma rows (fp32 -> fp16), 112 halves this chunk ----
#pragma unroll
        for (int i = 0; i < 7; i++) {
            int idx = tid + i * 256;          // 0..1791
            int r = idx / 14, u = idx - r * 14;
            int kf = c * 28 + 2 * u;          // float4 index within 50-long row
            float4 a0 = (kf     < 50) ? ma4[(m0 + r) * 50 + kf]     : f4z;
            float4 a1 = (kf + 1 < 50) ? ma4[(m0 + r) * 50 + kf + 1] : f4z;
            sts_h8(sb + (uint32_t)(r * RSTRB + u * 16), a0, a1);
        }
        // ---- stage B tile: node rows (emb | embt[sct]) ----
#pragma unroll
        for (int i = 0; i < 7; i++) {
            int idx = tid + i * 256;
            int r = idx / 14, u = idx - r * 14;
            int kf = c * 28 + 2 * u;
            int n = n0 + r + 1; if (n > NNODE - 1) n = NNODE - 1;
            int ct = sct[r];
            float4 b0 = f4z, b1 = f4z;
            if (kf < 25)      b0 = emb4[(size_t)n * 25 + kf];
            else if (kf < 50) b0 = embt4[(size_t)ct * 25 + (kf - 25)];
            int k1 = kf + 1;
            if (k1 < 25)      b1 = emb4[(size_t)n * 25 + k1];
            else if (k1 < 50) b1 = embt4[(size_t)ct * 25 + (k1 - 25)];
            sts_h8(sb + (uint32_t)TILEB + (uint32_t)(r * RSTRB + u * 16), b0, b1);
        }
        __syncthreads();

        // ---- compute 7 k16-steps ----
#pragma unroll
        for (int ks = 0; ks < 7; ks++) {
            const uint32_t kadd = (uint32_t)(ks * 32);   // 16 halves
            uint32_t af[4][4], bf[4][2];
#pragma unroll
            for (int mt = 0; mt < 4; mt++)
                ldsm_x4(af[mt][0], af[mt][1], af[mt][2], af[mt][3], baseA[mt] + kadd);
#pragma unroll
            for (int p = 0; p < 2; p++) {
                uint32_t r0, r1, r2, r3;
                ldsm_x4(r0, r1, r2, r3, baseB[p] + kadd);
                bf[2 * p][0] = r0;     bf[2 * p][1] = r1;
                bf[2 * p + 1][0] = r2; bf[2 * p + 1][1] = r3;
            }
#pragma unroll
            for (int mt = 0; mt < 4; mt++)
#pragma unroll
                for (int nt = 0; nt < 4; nt++)
                    mma_f16(acc[mt][nt],
                            af[mt][0], af[mt][1], af[mt][2], af[mt][3],
                            bf[nt][0], bf[nt][1]);
        }
    }
    __syncthreads();

    // ---- epilogue: stage through smem, store coalesced ----
    float* Cs = sm2;  // 128 x CSTR floats (overlaps tiles; compute is done)
#pragma unroll
    for (int mt = 0; mt < 4; mt++) {
        int r1 = wm * 64 + mt * 16 + (lane >> 2);
#pragma unroll
        for (int nt = 0; nt < 4; nt++) {
            int cc = wn * 32 + nt * 8 + 2 * (lane & 3);
            Cs[r1 * CSTR + cc]           = acc[mt][nt][0];
            Cs[r1 * CSTR + cc + 1]       = acc[mt][nt][1];
            Cs[(r1 + 8) * CSTR + cc]     = acc[mt][nt][2];
            Cs[(r1 + 8) * CSTR + cc + 1] = acc[mt][nt][3];
        }
    }
    __syncthreads();

    for (int idx = tid; idx < 128 * 128; idx += 256) {
        int r = idx >> 7, cc = idx & 127;
        int n = n0 + cc;
        if (n < NOUT)
            out[(size_t)(m0 + r) * NOUT + n] = Cs[r * CSTR + cc];
    }
}

// ---------------------------------------------------------------------------
// launch
// ---------------------------------------------------------------------------
extern "C" void kernel_launch(void* const* d_in, const int* in_sizes, int n_in,
                              void* d_out, int out_size) {
    (void)in_sizes; (void)n_in; (void)out_size;
    const float* re     = (const float*)d_in[0];
    const float* ret    = (const float*)d_in[1];
    const float* mask   = (const float*)d_in[2];
    const float* maskt  = (const float*)d_in[3];
    const int*   alias  = (const int*)d_in[4];
    const int*   aliast = (const int*)d_in[5];
    const int*   csort  = (const int*)d_in[6];
    const float* emb    = (const float*)d_in[7];
    const float* embt   = (const float*)d_in[8];
    const float* w1     = (const float*)d_in[9];
    const float* w2     = (const float*)d_in[10];
    const float* w3     = (const float*)d_in[11];
    const float* v      = (const float*)d_in[12];
    const float* bias   = (const float*)d_in[13];
    float* out = (float*)d_out;

    const size_t sm1 = (size_t)16440 * sizeof(float);   // 65,760 B
    const size_t sm2 = (size_t)P2_SMEM;                 // 68,160 B
    cudaFuncSetAttribute(phase1_kernel, cudaFuncAttributeMaxDynamicSharedMemorySize, (int)sm1);
    cudaFuncSetAttribute(phase2_kernel, cudaFuncAttributeMaxDynamicSharedMemorySize, (int)sm2);

    phase1_kernel<<<BB, 256, sm1>>>(re, ret, mask, maskt, alias, aliast,
                                    w1, w2, w3, v, bias);

    dim3 grid2(2, (NOUT + 127) / 128, 1);  // batch-tile fast -> emb L2 reuse
    phase2_kernel<<<grid2, 256, sm2>>>(emb, embt, csort, out);
}

// round 11
// speedup vs baseline: 1.3831x; 1.3831x over previous
#include <cuda_runtime.h>
#include <cuda_fp16.h>
#include <cstdint>
#include <math.h>

#define BB 256
#define TT 40
#define DD 100
#define D2 200
#define NNODE 200000
#define NTYPE 1000
#define NOUT 199999   // N_NODE - 1
#define KP 256        // padded K for phase 2 (layout: [emb 100 | 0x28 | embt 100 | 0x28])

// device-global scratch (no allocation allowed)
__device__ __align__(16) __half g_emb16[(size_t)NNODE * 128];   // 51.2 MB
__device__ __align__(16) __half g_embt16[(size_t)NTYPE * 128];  // 256 KB
__device__ __align__(16) __half g_ma16[BB * KP];                // 128 KB

// ---------------------------------------------------------------------------
// helpers
// ---------------------------------------------------------------------------
__device__ __forceinline__ unsigned long long pack2(float lo, float hi) {
    unsigned long long r;
    asm("mov.b64 %0, {%1,%2};" : "=l"(r) : "f"(lo), "f"(hi));
    return r;
}
__device__ __forceinline__ void ffma2(unsigned long long& d,
                                      unsigned long long a, unsigned long long b) {
    asm("fma.rn.f32x2 %0, %1, %2, %0;" : "+l"(d) : "l"(a), "l"(b));
}
__device__ __forceinline__ float2 unpack2(unsigned long long v) {
    float2 f;
    asm("mov.b64 {%0,%1}, %2;" : "=f"(f.x), "=f"(f.y) : "l"(v));
    return f;
}

__device__ __forceinline__ void mma_f16(float d[4],
                                        uint32_t a0, uint32_t a1, uint32_t a2, uint32_t a3,
                                        uint32_t b0, uint32_t b1) {
    asm volatile(
        "mma.sync.aligned.m16n8k16.row.col.f32.f16.f16.f32 "
        "{%0,%1,%2,%3}, {%4,%5,%6,%7}, {%8,%9}, {%0,%1,%2,%3};\n"
        : "+f"(d[0]), "+f"(d[1]), "+f"(d[2]), "+f"(d[3])
        : "r"(a0), "r"(a1), "r"(a2), "r"(a3), "r"(b0), "r"(b1));
}

__device__ __forceinline__ void ldsm_x4(uint32_t& r0, uint32_t& r1,
                                        uint32_t& r2, uint32_t& r3, uint32_t addr) {
    asm volatile("ldmatrix.sync.aligned.m8n8.x4.shared.b16 {%0,%1,%2,%3}, [%4];"
                 : "=r"(r0), "=r"(r1), "=r"(r2), "=r"(r3) : "r"(addr));
}

__device__ __forceinline__ void cp16(uint32_t dst, const void* src) {
    asm volatile("cp.async.cg.shared.global [%0], [%1], 16;"
                 :: "r"(dst), "l"(src) : "memory");
}
__device__ __forceinline__ void cp_commit() {
    asm volatile("cp.async.commit_group;" ::: "memory");
}
template <int N>
__device__ __forceinline__ void cp_wait() {
    asm volatile("cp.async.wait_group %0;" :: "n"(N) : "memory");
}

// 8 fp32 -> uint4 of 8 halves
__device__ __forceinline__ uint4 h8_of(float4 a, float4 b) {
    __half2 h0 = __float22half2_rn(make_float2(a.x, a.y));
    __half2 h1 = __float22half2_rn(make_float2(a.z, a.w));
    __half2 h2 = __float22half2_rn(make_float2(b.x, b.y));
    __half2 h3 = __float22half2_rn(make_float2(b.z, b.w));
    uint4 u;
    u.x = *reinterpret_cast<uint32_t*>(&h0);
    u.y = *reinterpret_cast<uint32_t*>(&h1);
    u.z = *reinterpret_cast<uint32_t*>(&h2);
    u.w = *reinterpret_cast<uint32_t*>(&h3);
    return u;
}

// ---------------------------------------------------------------------------
// prep: fp32 -> fp16 padded copies of embedding tables
// unit = 16 output bytes (8 halves). emb rows: 100 floats -> 128 halves.
// ---------------------------------------------------------------------------
#define EMB_UNITS (NNODE * 16)
#define EMBT_UNITS (NTYPE * 16)

__global__ __launch_bounds__(256) void prep_kernel(
    const float* __restrict__ emb,    // [N_NODE, 100]
    const float* __restrict__ embt)   // [N_TYPE, 100]
{
    int uid = blockIdx.x * 256 + threadIdx.x;
    const float4 z = make_float4(0.f, 0.f, 0.f, 0.f);
    if (uid < EMB_UNITS) {
        int row = uid >> 4, u = uid & 15;
        int fb = 8 * u;
        const float4* src = (const float4*)(emb + (size_t)row * DD);
        float4 f0 = (fb < DD) ? src[fb >> 2] : z;
        float4 f1 = (fb + 4 < DD) ? src[(fb >> 2) + 1] : z;
        *(uint4*)(g_emb16 + (size_t)row * 128 + fb) = h8_of(f0, f1);
    } else if (uid < EMB_UNITS + EMBT_UNITS) {
        int t = uid - EMB_UNITS;
        int row = t >> 4, u = t & 15;
        int fb = 8 * u;
        const float4* src = (const float4*)(embt + (size_t)row * DD);
        float4 f0 = (fb < DD) ? src[fb >> 2] : z;
        float4 f1 = (fb + 4 < DD) ? src[(fb >> 2) + 1] : z;
        *(uint4*)(g_embt16 + (size_t)row * 128 + fb) = h8_of(f0, f1);
    }
}

// ---------------------------------------------------------------------------
// Phase 1: one CTA per batch element; writes g_ma16[b][0..255] (padded layout)
// ---------------------------------------------------------------------------
__global__ __launch_bounds__(256) void phase1_kernel(
    const float* __restrict__ re,     // [B,U,D]
    const float* __restrict__ ret,    // [B,U,D]
    const float* __restrict__ mask,   // [B,T]
    const float* __restrict__ maskt,  // [B,T]
    const int*   __restrict__ alias,  // [B,T]
    const int*   __restrict__ aliast, // [B,T]
    const float* __restrict__ w1,     // [2D,2D]
    const float* __restrict__ w2,     // [2D,2D]
    const float* __restrict__ w3,     // [2D,2D]
    const float* __restrict__ v,      // [2D]
    const float* __restrict__ bias)   // [2D]
{
    extern __shared__ float sm1[];
    float* sh    = sm1;            // [40][200]
    float* cbuf  = sm1 + 8000;     // [40][200]
    float* coefs = sm1 + 16000;    // [40]
    float* svec  = sm1 + 16040;    // [200]
    float* lastv = sm1 + 16240;    // [200]
    __shared__ int sa[TT], sat[TT], slast[2];

    const int b = blockIdx.x;
    const int tid = threadIdx.x;
    const int j = tid;

    // zero the padded fp16 row (pads stay zero; data slots overwritten below)
    g_ma16[b * KP + tid] = __float2half(0.f);

    if (tid < TT) {
        sa[tid]  = alias[b * TT + tid];
        sat[tid] = aliast[b * TT + tid];
    }
    if (tid == 0) {
        float s = 0.f, st = 0.f;
        for (int t = 0; t < TT; t++) { s += mask[b * TT + t]; st += maskt[b * TT + t]; }
        int rm  = (int)(s  + 0.5f); rm  = rm  < 1 ? 1 : (rm  > TT ? TT : rm);
        int rmt = (int)(st + 0.5f); rmt = rmt < 1 ? 1 : (rmt > TT ? TT : rmt);
        slast[0] = alias[b * TT + rm - 1];
        slast[1] = aliast[b * TT + rmt - 1];
    }
    __syncthreads();

    for (int idx = tid; idx < TT * D2; idx += 256) {
        int t = idx / D2, k = idx - t * D2;
        sh[idx] = (k < DD) ? re[(b * TT + sa[t]) * DD + k]
                           : ret[(b * TT + sat[t]) * DD + (k - DD)];
    }
    if (tid < D2) {
        lastv[tid] = (tid < DD) ? re[(b * TT + slast[0]) * DD + tid]
                                : ret[(b * TT + slast[1]) * DD + (tid - DD)];
    }
    __syncthreads();

    float lpj = 0.f;
    if (j < D2) {
        for (int k = 0; k < D2; k++) lpj += lastv[k] * w1[k * D2 + j];
    }

    if (j < D2) {
        unsigned long long acc2[TT];
        const unsigned long long z = pack2(0.f, 0.f);
#pragma unroll
        for (int t = 0; t < TT; t++) acc2[t] = z;
        for (int k = 0; k < D2; k += 4) {
            unsigned long long w01 = pack2(w2[(k + 0) * D2 + j], w2[(k + 1) * D2 + j]);
            unsigned long long w23 = pack2(w2[(k + 2) * D2 + j], w2[(k + 3) * D2 + j]);
#pragma unroll
            for (int t = 0; t < TT; t++) {
                ulonglong2 s2 = *(const ulonglong2*)&sh[t * D2 + k];
                ffma2(acc2[t], s2.x, w01);
                ffma2(acc2[t], s2.y, w23);
            }
        }
        float vj = v[j], bj = bias[j];
#pragma unroll
        for (int t = 0; t < TT; t++) {
            float2 u = unpack2(acc2[t]);
            float x = lpj + u.x + u.y + bj;
            float e = __expf(-x);
            float mval = __fdividef(1.f, 1.f + e);
            cbuf[t * D2 + j] = mval * vj;
        }
    }
    __syncthreads();

    if (tid < TT) {
        float c = 0.f;
        for (int jj = 0; jj < D2; jj++) c += cbuf[tid * D2 + jj];
        coefs[tid] = c * mask[b * TT + tid];
    }
    __syncthreads();

    if (tid < D2) {
        float s = 0.f;
#pragma unroll
        for (int t = 0; t < TT; t++) s += coefs[t] * sh[t * D2 + tid];
        svec[tid] = s;
    }
    __syncthreads();

    if (j < D2) {
        float m = 0.f;
        for (int k = 0; k < D2; k++) m += svec[k] * w3[k * D2 + j];
        int pos = (j < DD) ? j : (j + 28);   // padded layout
        g_ma16[b * KP + pos] = __float2half(m);
    }
}

// ---------------------------------------------------------------------------
// Phase 2: logits[256][199999] = ma16 @ b_emb16^T, fp16 mma.m16n8k16.
// BM=BN=128, K=256 in 4 chunks of 64 halves (128 B per row per chunk).
// cp.async.cg staging, double-buffered, XOR-swizzled smem (conflict-free
// ldmatrix). Epilogue: smem transpose -> coalesced 128B warp stores.
// ---------------------------------------------------------------------------
#define CHB   128                 // bytes per row per chunk
#define TILEB (128 * CHB)         // 16384 B per operand tile per chunk
#define BUFB  (2 * TILEB)         // A+B per chunk stage = 32768
#define SCT_OFF 67584             // after epilogue Cs region (128*132*4)
#define P2_SMEM (SCT_OFF + 512)
#define CSTR  132                 // epilogue smem stride (floats)

__global__ __launch_bounds__(256, 2) void phase2_kernel(
    float* __restrict__ out)          // [256, 199999]
{
    extern __shared__ __align__(16) float sm2[];
    const uint32_t sb = (uint32_t)__cvta_generic_to_shared(sm2);
    int* sct = (int*)((char*)sm2 + SCT_OFF);

    const int tid  = threadIdx.x;
    const int wid  = tid >> 5;
    const int lane = tid & 31;
    const int m0   = blockIdx.x * 128;   // batch tile
    const int n0   = blockIdx.y * 128;   // node tile
    const int wm = wid >> 2;   // 0..1 -> 64 batch rows
    const int wn = wid & 3;    // 0..3 -> 32 node cols

    // (sct filled by phase2_idx_kernel? no — csort gather folded here via
    //  global load; indices staged once)
    // NOTE: csort gather is done in issue lambda via sct[] staged below.

    // fragment row offsets (validated mapping from R10, plus XOR swizzle)
    const int hiA = (lane >> 4) & 1;
    const int hiB = (lane >> 3) & 1;
    int rowA[4], rowB[2];
#pragma unroll
    for (int mt = 0; mt < 4; mt++) rowA[mt] = wm * 64 + mt * 16 + (lane & 15);
#pragma unroll
    for (int p = 0; p < 2; p++)
        rowB[p] = wn * 32 + p * 16 + ((lane >> 4) & 1) * 8 + (lane & 7);

    float acc[4][4][4];
#pragma unroll
    for (int mt = 0; mt < 4; mt++)
#pragma unroll
        for (int nt = 0; nt < 4; nt++)
#pragma unroll
            for (int r = 0; r < 4; r++) acc[mt][nt][r] = 0.f;

    // stage csort indices for this node tile (needs to happen before issue)
    // done via plain loads; sct lives above the staging buffers.
    // (filled by all threads, then sync)
    // --- begin ---
    // (d_csort passed via const pointer below)
    // placeholder; actual fill in launch wrapper variant
    // --- end ---
    // NOTE: csort pointer comes in through kernel argument list:
    //       see signature extension below.
    (void)sct;

    // The staging lambda and mainloop are emitted in phase2_body.
    // (unreachable placeholder removed by compiler)
    // -- real implementation continues in phase2_impl below --
    // To keep a single kernel, csort is an argument:
    //   (refactored: this kernel is replaced by phase2_impl)
    out += 0;
}

// real phase2 (single definition used by launcher)
__global__ __launch_bounds__(256, 2) void phase2_impl(
    const int* __restrict__ csort,
    float* __restrict__ out)          // [256, 199999]
{
    extern __shared__ __align__(16) float sm2[];
    const uint32_t sb = (uint32_t)__cvta_generic_to_shared(sm2);
    int* sct = (int*)((char*)sm2 + SCT_OFF);

    const int tid  = threadIdx.x;
    const int wid  = tid >> 5;
    const int lane = tid & 31;
    const int m0   = blockIdx.x * 128;   // batch tile
    const int n0   = blockIdx.y * 128;   // node tile
    const int wm = wid >> 2;
    const int wn = wid & 3;

    for (int i = tid; i < 128; i += 256) {
        int n = n0 + i + 1; if (n > NNODE - 1) n = NNODE - 1;
        sct[i] = csort[n];
    }
    __syncthreads();

    const int hiA = (lane >> 4) & 1;
    const int hiB = (lane >> 3) & 1;
    int rowAoff[4], swA[4], rowBoff[2], swB[2];
#pragma unroll
    for (int mt = 0; mt < 4; mt++) {
        int r = wm * 64 + mt * 16 + (lane & 15);
        rowAoff[mt] = r * CHB; swA[mt] = r & 7;
    }
#pragma unroll
    for (int p = 0; p < 2; p++) {
        int r = wn * 32 + p * 16 + ((lane >> 4) & 1) * 8 + (lane & 7);
        rowBoff[p] = r * CHB; swB[p] = r & 7;
    }

    float acc[4][4][4];
#pragma unroll
    for (int mt = 0; mt < 4; mt++)
#pragma unroll
        for (int nt = 0; nt < 4; nt++)
#pragma unroll
            for (int r = 0; r < 4; r++) acc[mt][nt][r] = 0.f;

    // ---- issue one chunk: 2048 16-B units, 8 per thread ----
    auto issue_chunk = [&](int c) {
        const uint32_t buf = sb + (uint32_t)((c & 1) * BUFB);
#pragma unroll
        for (int i = 0; i < 8; i++) {
            int uid = tid + i * 256;
            int tile = uid >> 10;            // 0 = A(ma), 1 = B(nodes)
            int r = (uid >> 3) & 127;
            int u = uid & 7;
            uint32_t dst = buf + (uint32_t)(tile * TILEB + r * CHB
                                            + ((u ^ (r & 7)) << 4));
            const __half* src;
            if (tile == 0) {
                src = g_ma16 + (size_t)(m0 + r) * KP + c * 64 + u * 8;
            } else if (c < 2) {
                int n = n0 + r + 1; if (n > NNODE - 1) n = NNODE - 1;
                src = g_emb16 + (size_t)n * 128 + c * 64 + u * 8;
            } else {
                src = g_embt16 + (size_t)sct[r] * 128 + (c - 2) * 64 + u * 8;
            }
            cp16(dst, src);
        }
        cp_commit();
    };

    issue_chunk(0);
    issue_chunk(1);

#pragma unroll
    for (int c = 0; c < 4; c++) {
        if (c < 3) cp_wait<1>(); else cp_wait<0>();
        __syncthreads();

        const uint32_t bufo = (uint32_t)((c & 1) * BUFB);
#pragma unroll
        for (int ks = 0; ks < 4; ks++) {
            uint32_t af[4][4], bf[4][2];
            const int uA = 2 * ks + hiA;
            const int uB = 2 * ks + hiB;
#pragma unroll
            for (int mt = 0; mt < 4; mt++) {
                uint32_t addr = sb + bufo + (uint32_t)rowAoff[mt]
                              + (uint32_t)((uA ^ swA[mt]) << 4);
                ldsm_x4(af[mt][0], af[mt][1], af[mt][2], af[mt][3], addr);
            }
#pragma unroll
            for (int p = 0; p < 2; p++) {
                uint32_t addr = sb + bufo + (uint32_t)TILEB + (uint32_t)rowBoff[p]
                              + (uint32_t)((uB ^ swB[p]) << 4);
                uint32_t r0, r1, r2, r3;
                ldsm_x4(r0, r1, r2, r3, addr);
                bf[2 * p][0] = r0;     bf[2 * p][1] = r1;
                bf[2 * p + 1][0] = r2; bf[2 * p + 1][1] = r3;
            }
#pragma unroll
            for (int mt = 0; mt < 4; mt++)
#pragma unroll
                for (int nt = 0; nt < 4; nt++)
                    mma_f16(acc[mt][nt],
                            af[mt][0], af[mt][1], af[mt][2], af[mt][3],
                            bf[nt][0], bf[nt][1]);
        }
        __syncthreads();
        if (c < 2) issue_chunk(c + 2);
    }

    // ---- epilogue: smem transpose -> coalesced stores ----
    float* Cs = sm2;
#pragma unroll
    for (int mt = 0; mt < 4; mt++) {
        int r1 = wm * 64 + mt * 16 + (lane >> 2);
#pragma unroll
        for (int nt = 0; nt < 4; nt++) {
            int cc = wn * 32 + nt * 8 + 2 * (lane & 3);
            Cs[r1 * CSTR + cc]           = acc[mt][nt][0];
            Cs[r1 * CSTR + cc + 1]       = acc[mt][nt][1];
            Cs[(r1 + 8) * CSTR + cc]     = acc[mt][nt][2];
            Cs[(r1 + 8) * CSTR + cc + 1] = acc[mt][nt][3];
        }
    }
    __syncthreads();

    for (int idx = tid; idx < 128 * 128; idx += 256) {
        int r = idx >> 7, cc = idx & 127;
        int n = n0 + cc;
        if (n < NOUT)
            out[(size_t)(m0 + r) * NOUT + n] = Cs[r * CSTR + cc];
    }
}

// ---------------------------------------------------------------------------
// launch
// ---------------------------------------------------------------------------
extern "C" void kernel_launch(void* const* d_in, const int* in_sizes, int n_in,
                              void* d_out, int out_size) {
    (void)in_sizes; (void)n_in; (void)out_size;
    const float* re     = (const float*)d_in[0];
    const float* ret    = (const float*)d_in[1];
    const float* mask   = (const float*)d_in[2];
    const float* maskt  = (const float*)d_in[3];
    const int*   alias  = (const int*)d_in[4];
    const int*   aliast = (const int*)d_in[5];
    const int*   csort  = (const int*)d_in[6];
    const float* emb    = (const float*)d_in[7];
    const float* embt   = (const float*)d_in[8];
    const float* w1     = (const float*)d_in[9];
    const float* w2     = (const float*)d_in[10];
    const float* w3     = (const float*)d_in[11];
    const float* v      = (const float*)d_in[12];
    const float* bias   = (const float*)d_in[13];
    float* out = (float*)d_out;

    const size_t sm1 = (size_t)16440 * sizeof(float);   // 65,760 B
    const size_t sm2 = (size_t)P2_SMEM;                 // 68,096 B
    cudaFuncSetAttribute(phase1_kernel, cudaFuncAttributeMaxDynamicSharedMemorySize, (int)sm1);
    cudaFuncSetAttribute(phase2_impl, cudaFuncAttributeMaxDynamicSharedMemorySize, (int)sm2);

    const int prep_blocks = (EMB_UNITS + EMBT_UNITS + 255) / 256;
    prep_kernel<<<prep_blocks, 256>>>(emb, embt);

    phase1_kernel<<<BB, 256, sm1>>>(re, ret, mask, maskt, alias, aliast,
                                    w1, w2, w3, v, bias);

    dim3 grid2(2, (NOUT + 127) / 128, 1);  // batch-tile fast -> emb16 L2 reuse
    phase2_impl<<<grid2, 256, sm2>>>(csort, out);
}